// round 6
// baseline (speedup 1.0000x reference)
#include <cuda_runtime.h>
#include <math.h>

#define BN_EPS 1e-5f
#define NB 2
#define NC 128
#define NPT 4096
#define KK 20
#define CHH 64
#define CDD 16

// ---------------- device scratch (no allocations allowed) ----------------
__device__ int   d_idx[NB * NPT * KK];
__device__ float d_P[NB * NPT * NC];       // [b][n][c]  c<64: xyz-half, c>=64: feat-half
__device__ float d_Q[NB * NPT * NC];
__device__ float d_fenc[NB * NPT * NC];    // [b][n][c]
__device__ float d_f1[NB * NPT * CDD];     // [b][n][o]
__device__ float d_f2[NB * NPT * CDD];
__device__ float d_fsp[NPT];
__device__ float d_fch[CDD];
__device__ float d_fchpart[512 * CDD];
// folded weights
__device__ float d_w1p[CHH * 3], d_w1q[CHH * 3], d_b1f[CHH];
__device__ float d_w2p[CHH * NC], d_w2q[CHH * NC], d_b2f[CHH];
__device__ float d_wupf[NC * CDD], d_bupf[NC];

// ---------------- prep: fold BN + split weights ----------------
__global__ void prep_kernel(const float* w_mlp1, const float* b_mlp1,
                            const float* g1, const float* be1, const float* m1, const float* v1,
                            const float* w_mlp2, const float* b_mlp2,
                            const float* g2, const float* be2, const float* m2, const float* v2,
                            const float* w_up, const float* b_up,
                            const float* gu, const float* beu, const float* mu, const float* vu)
{
    int tid = threadIdx.x;
    for (int c = tid; c < CHH; c += blockDim.x) {
        float s = g1[c] * rsqrtf(v1[c] + BN_EPS);
        float t = be1[c] - m1[c] * s;
        d_b1f[c] = s * b_mlp1[c] + t;
        #pragma unroll
        for (int j = 0; j < 3; ++j) {
            float wx = w_mlp1[c * 6 + j];
            float wc = w_mlp1[c * 6 + 3 + j];
            d_w1p[c * 3 + j] = s * wx;
            d_w1q[c * 3 + j] = s * (wc - wx);
        }
        float s2 = g2[c] * rsqrtf(v2[c] + BN_EPS);
        float t2 = be2[c] - m2[c] * s2;
        d_b2f[c] = s2 * b_mlp2[c] + t2;
    }
    for (int i = tid; i < CHH * NC; i += blockDim.x) {
        int c = i >> 7;
        float s2 = g2[c] * rsqrtf(v2[c] + BN_EPS);
        int j = i & 127;
        float wa = w_mlp2[c * 256 + j];
        float wb = w_mlp2[c * 256 + 128 + j];
        d_w2p[i] = s2 * wa;
        d_w2q[i] = s2 * (wb - wa);
    }
    for (int i = tid; i < NC * CDD; i += blockDim.x) {
        int c = i >> 4;
        float su = gu[c] * rsqrtf(vu[c] + BN_EPS);
        d_wupf[i] = su * w_up[i];
    }
    for (int c = tid; c < NC; c += blockDim.x) {
        float su = gu[c] * rsqrtf(vu[c] + BN_EPS);
        d_bupf[c] = su * b_up[c] + (beu[c] - mu[c] * su);
    }
}

// ---------------- KNN: warp per row, per-thread top-20 + warp merge ----------------
__global__ void __launch_bounds__(256) knn_kernel(const float* __restrict__ xyz)
{
    __shared__ float sx[NPT];
    __shared__ float sy[NPT];
    __shared__ float sz[NPT];
    int b = blockIdx.y;
    const float* base = xyz + b * 3 * NPT;
    for (int i = threadIdx.x; i < NPT; i += 256) {
        sx[i] = base[i];
        sy[i] = base[NPT + i];
        sz[i] = base[2 * NPT + i];
    }
    __syncthreads();

    int warp = threadIdx.x >> 5;
    int lane = threadIdx.x & 31;
    int n = blockIdx.x * 8 + warp;
    float xn = sx[n], yn = sy[n], zn = sz[n];

    float bd[KK];
    int   bj[KK];
    #pragma unroll
    for (int i = 0; i < KK; ++i) { bd[i] = 1e30f; bj[i] = 0; }
    float worst = 1e30f;

    for (int j = lane; j < NPT; j += 32) {
        float dx = sx[j] - xn;
        float dy = sy[j] - yn;
        float dz = sz[j] - zn;
        float d = fmaf(dx, dx, fmaf(dy, dy, dz * dz));
        if (d < worst) {
            int p = KK - 1;
            while (p > 0 && bd[p - 1] > d) {
                bd[p] = bd[p - 1]; bj[p] = bj[p - 1]; --p;
            }
            bd[p] = d; bj[p] = j;
            worst = bd[KK - 1];
        }
    }

    // warp merge of 32 sorted lists -> global top-20
    int ptr = 0;
    int out_base = (b * NPT + n) * KK;
    for (int r = 0; r < KK; ++r) {
        float v = (ptr < KK) ? bd[ptr] : 1e30f;
        float mv = v; int ml = lane;
        #pragma unroll
        for (int off = 16; off > 0; off >>= 1) {
            float ov = __shfl_down_sync(0xffffffffu, mv, off);
            int   ol = __shfl_down_sync(0xffffffffu, ml, off);
            if (ov < mv) { mv = ov; ml = ol; }
        }
        ml = __shfl_sync(0xffffffffu, ml, 0);
        int cj = bj[(ptr < KK) ? ptr : (KK - 1)];
        int wj = __shfl_sync(0xffffffffu, cj, ml);
        if (lane == 0) d_idx[out_base + r] = wj;
        if (lane == ml) ptr++;
    }
}

// ---------------- PQ: per-point projections (feat 128->64 for P and Q, plus xyz MLP) ----
__global__ void __launch_bounds__(128) pq_kernel(const float* __restrict__ xyz,
                                                 const float* __restrict__ features)
{
    __shared__ __align__(16) float s_f[NC * 16];  // [j][p]
    __shared__ float s_w[64 * 129];               // [j_local][cout] padded
    __shared__ float s_x[3 * 16];                 // [j][p]
    int b = blockIdx.y;
    int n0 = blockIdx.x * 16;
    int tid = threadIdx.x;

    for (int i = tid; i < NC * 16; i += 128) {
        int j = i >> 4, p = i & 15;
        s_f[i] = features[b * NC * NPT + j * NPT + n0 + p];
    }
    if (tid < 48) {
        int j = tid >> 4, p = tid & 15;
        s_x[tid] = xyz[b * 3 * NPT + j * NPT + n0 + p];
    }

    float acc[16];
    #pragma unroll
    for (int p = 0; p < 16; ++p) acc[p] = 0.f;
    int cout = tid;

    for (int jc = 0; jc < NC; jc += 64) {
        __syncthreads();
        for (int i = tid; i < 64 * 128; i += 128) {
            int jl = i & 63, co = i >> 6;
            float w = (co < 64) ? d_w2p[co * NC + jc + jl]
                                : d_w2q[(co - 64) * NC + jc + jl];
            s_w[jl * 129 + co] = w;
        }
        __syncthreads();
        #pragma unroll 4
        for (int jl = 0; jl < 64; ++jl) {
            float w = s_w[jl * 129 + cout];
            const float4* f4 = (const float4*)(s_f + (jc + jl) * 16);
            float fv[16];
            *(float4*)(fv + 0)  = f4[0];
            *(float4*)(fv + 4)  = f4[1];
            *(float4*)(fv + 8)  = f4[2];
            *(float4*)(fv + 12) = f4[3];
            #pragma unroll
            for (int p = 0; p < 16; ++p) acc[p] = fmaf(w, fv[p], acc[p]);
        }
    }

    if (cout < 64) {
        #pragma unroll
        for (int p = 0; p < 16; ++p)
            d_P[(b * NPT + n0 + p) * NC + 64 + cout] = acc[p];
        float w0 = d_w1p[cout * 3], w1 = d_w1p[cout * 3 + 1], w2 = d_w1p[cout * 3 + 2];
        #pragma unroll
        for (int p = 0; p < 16; ++p)
            d_P[(b * NPT + n0 + p) * NC + cout] =
                fmaf(w0, s_x[p], fmaf(w1, s_x[16 + p], w2 * s_x[32 + p]));
    } else {
        int cq = cout - 64;
        float bb = d_b2f[cq];
        #pragma unroll
        for (int p = 0; p < 16; ++p)
            d_Q[(b * NPT + n0 + p) * NC + 64 + cq] = acc[p] + bb;
        float w0 = d_w1q[cq * 3], w1 = d_w1q[cq * 3 + 1], w2 = d_w1q[cq * 3 + 2];
        float b1 = d_b1f[cq];
        #pragma unroll
        for (int p = 0; p < 16; ++p)
            d_Q[(b * NPT + n0 + p) * NC + cq] =
                fmaf(w0, s_x[p], fmaf(w1, s_x[16 + p], fmaf(w2, s_x[32 + p], b1)));
    }
}

// ---------------- f_enc: gather neighbors' P, max, add Q, relu ----------------
__global__ void __launch_bounds__(128) fenc_kernel()
{
    __shared__ int s_idx[8 * KK];
    int b = blockIdx.y, n0 = blockIdx.x * 8, tid = threadIdx.x;
    for (int i = tid; i < 8 * KK; i += 128)
        s_idx[i] = d_idx[(b * NPT + n0) * KK + i];
    __syncthreads();
    const float* Pb = d_P + b * NPT * NC;
    for (int p = 0; p < 8; ++p) {
        int n = n0 + p;
        float q = d_Q[(b * NPT + n) * NC + tid];
        float m = -1e30f;
        #pragma unroll
        for (int k = 0; k < KK; ++k) {
            int j = s_idx[p * KK + k];
            m = fmaxf(m, Pb[j * NC + tid]);
        }
        d_fenc[(b * NPT + n) * NC + tid] = fmaxf(q + m, 0.f);
    }
}

// ---------------- down-proj f1/f2 + f_space + f_channel partials ----------------
__global__ void __launch_bounds__(256) down_kernel(const float* __restrict__ wd1,
                                                   const float* __restrict__ wd2)
{
    __shared__ float s_fe[8 * NC];
    __shared__ float s_w[32 * 129];
    __shared__ float s_part[CDD * 9];
    int b = blockIdx.y, n0 = blockIdx.x * 8, tid = threadIdx.x;

    for (int i = tid; i < 32 * NC; i += 256) {
        int o = i >> 7, c = i & 127;
        float w = (o < 16) ? wd1[o * NC + c] : wd2[(o - 16) * NC + c];
        s_w[o * 129 + c] = w;
    }
    for (int i = tid; i < 8 * NC; i += 256)
        s_fe[i] = d_fenc[(b * NPT + n0) * NC + i];
    __syncthreads();

    int o = tid & 31, p = tid >> 5;
    const float* wr = s_w + o * 129;
    const float* fr = s_fe + p * NC;
    float a = 0.f;
    #pragma unroll 8
    for (int c = 0; c < NC; ++c) a = fmaf(wr[c], fr[c], a);
    a = fmaxf(a, 0.f);
    int n = n0 + p;
    if (o < 16) {
        d_f1[(b * NPT + n) * CDD + o] = a;
        if (b == 0) s_part[o * 9 + p] = a;
    } else {
        d_f2[(b * NPT + n) * CDD + (o - 16)] = a;
    }
    if (b == 0) {
        float v = (o >= 16) ? a : 0.f;
        #pragma unroll
        for (int off = 16; off > 0; off >>= 1)
            v += __shfl_down_sync(0xffffffffu, v, off);
        if (o == 0) d_fsp[n] = v * (1.f / 16.f);
        __syncthreads();
        if (tid < CDD) {
            float s = 0.f;
            #pragma unroll
            for (int p2 = 0; p2 < 8; ++p2) s += s_part[tid * 9 + p2];
            d_fchpart[blockIdx.x * CDD + tid] = s;
        }
    }
}

// ---------------- deterministic f_channel reduction ----------------
__global__ void fch_kernel()
{
    int o = threadIdx.x;
    float s = 0.f;
    for (int blk = 0; blk < 512; ++blk) s += d_fchpart[blk * CDD + o];
    d_fch[o] = s * (1.f / (float)NPT);
}

// ---------------- final: attention cross-term, up-proj+BN+relu, mish, transpose-store --
__global__ void __launch_bounds__(256) final_kernel(float* __restrict__ out)
{
    __shared__ float s_v[16 * 33];
    __shared__ float s_o[128 * 33];
    int b = blockIdx.y, n0 = blockIdx.x * 32, tid = threadIdx.x;

    for (int i = tid; i < 512; i += 256) {
        int o = i & 15, p = i >> 4;
        int n = n0 + p;
        float f1v = d_f1[(b * NPT + n) * CDD + o];
        float f2v = d_f2[(b * NPT + n) * CDD + o];
        float cross = sqrtf(fmaf(d_fch[o], d_fsp[n], 1e-12f));
        s_v[o * 33 + p] = cross + f1v + f2v;
    }
    __syncthreads();

    int c = tid & 127, ph = tid >> 7;
    float w16[16];
    #pragma unroll
    for (int o = 0; o < 16; ++o) w16[o] = d_wupf[c * CDD + o];
    float bup = d_bupf[c];

    for (int p = ph * 16; p < ph * 16 + 16; ++p) {
        float a = bup;
        #pragma unroll
        for (int o = 0; o < 16; ++o) a = fmaf(w16[o], s_v[o * 33 + p], a);
        float U = fmaxf(a, 0.f);
        float fe = d_fenc[(b * NPT + n0 + p) * NC + c];
        float x = fe - U;
        float sp = fmaxf(x, 0.f) + log1pf(expf(-fabsf(x)));
        s_o[c * 33 + p] = x * tanhf(sp);
    }
    __syncthreads();

    for (int i = tid; i < 128 * 32; i += 256) {
        int cc = i >> 5, p = i & 31;
        out[b * NC * NPT + cc * NPT + n0 + p] = s_o[cc * 33 + p];
    }
}

// ---------------- launch ----------------
extern "C" void kernel_launch(void* const* d_in, const int* in_sizes, int n_in,
                              void* d_out, int out_size)
{
    const float* xyz      = (const float*)d_in[0];
    const float* features = (const float*)d_in[1];
    const float* w_mlp1   = (const float*)d_in[2];
    const float* b_mlp1   = (const float*)d_in[3];
    const float* g1       = (const float*)d_in[4];
    const float* be1      = (const float*)d_in[5];
    const float* m1       = (const float*)d_in[6];
    const float* v1       = (const float*)d_in[7];
    const float* w_mlp2   = (const float*)d_in[8];
    const float* b_mlp2   = (const float*)d_in[9];
    const float* g2       = (const float*)d_in[10];
    const float* be2      = (const float*)d_in[11];
    const float* m2       = (const float*)d_in[12];
    const float* v2       = (const float*)d_in[13];
    const float* w_down1  = (const float*)d_in[14];
    const float* w_down2  = (const float*)d_in[15];
    const float* w_up     = (const float*)d_in[16];
    const float* b_up     = (const float*)d_in[17];
    const float* gu       = (const float*)d_in[18];
    const float* beu      = (const float*)d_in[19];
    const float* mu       = (const float*)d_in[20];
    const float* vu       = (const float*)d_in[21];
    // d_in[22] = k (always 20 for this problem; compiled in)

    prep_kernel<<<1, 256>>>(w_mlp1, b_mlp1, g1, be1, m1, v1,
                            w_mlp2, b_mlp2, g2, be2, m2, v2,
                            w_up, b_up, gu, beu, mu, vu);
    knn_kernel<<<dim3(NPT / 8, NB), 256>>>(xyz);
    pq_kernel<<<dim3(NPT / 16, NB), 128>>>(xyz, features);
    fenc_kernel<<<dim3(NPT / 8, NB), 128>>>();
    down_kernel<<<dim3(NPT / 8, NB), 256>>>(w_down1, w_down2);
    fch_kernel<<<1, CDD>>>();
    final_kernel<<<dim3(NPT / 32, NB), 256>>>((float*)d_out);
}

// round 7
// speedup vs baseline: 1.0022x; 1.0022x over previous
#include <cuda_runtime.h>
#include <math.h>

#define BN_EPS 1e-5f
#define NB 2
#define NC 128
#define NPT 4096
#define KK 20
#define CHH 64
#define CDD 16

// ---------------- device scratch (no allocations allowed) ----------------
__device__ int   d_idx[NB * NPT * KK];
__device__ float d_P[NB * NPT * NC];       // [b][n][c]  c<64: xyz-half, c>=64: feat-half
__device__ float d_Q[NB * NPT * NC];
__device__ float d_fenc[NB * NPT * NC];    // [b][n][c]
__device__ float d_f1[NB * NPT * CDD];     // [b][n][o]
__device__ float d_f2[NB * NPT * CDD];
__device__ float d_fsp[NPT];
__device__ float d_fch[CDD];
__device__ float d_fchpart[512 * CDD];
// folded weights
__device__ float d_w1p[CHH * 3], d_w1q[CHH * 3], d_b1f[CHH];
__device__ float d_w2p[CHH * NC], d_w2q[CHH * NC], d_b2f[CHH];
__device__ float d_wupf[NC * CDD], d_bupf[NC];

// ---------------- prep: fold BN + split weights ----------------
__global__ void prep_kernel(const float* w_mlp1, const float* b_mlp1,
                            const float* g1, const float* be1, const float* m1, const float* v1,
                            const float* w_mlp2, const float* b_mlp2,
                            const float* g2, const float* be2, const float* m2, const float* v2,
                            const float* w_up, const float* b_up,
                            const float* gu, const float* beu, const float* mu, const float* vu)
{
    int tid = threadIdx.x;
    for (int c = tid; c < CHH; c += blockDim.x) {
        float s = g1[c] * rsqrtf(v1[c] + BN_EPS);
        float t = be1[c] - m1[c] * s;
        d_b1f[c] = s * b_mlp1[c] + t;
        #pragma unroll
        for (int j = 0; j < 3; ++j) {
            float wx = w_mlp1[c * 6 + j];
            float wc = w_mlp1[c * 6 + 3 + j];
            d_w1p[c * 3 + j] = s * wx;
            d_w1q[c * 3 + j] = s * (wc - wx);
        }
        float s2 = g2[c] * rsqrtf(v2[c] + BN_EPS);
        float t2 = be2[c] - m2[c] * s2;
        d_b2f[c] = s2 * b_mlp2[c] + t2;
    }
    for (int i = tid; i < CHH * NC; i += blockDim.x) {
        int c = i >> 7;
        float s2 = g2[c] * rsqrtf(v2[c] + BN_EPS);
        int j = i & 127;
        float wa = w_mlp2[c * 256 + j];
        float wb = w_mlp2[c * 256 + 128 + j];
        d_w2p[i] = s2 * wa;
        d_w2q[i] = s2 * (wb - wa);
    }
    for (int i = tid; i < NC * CDD; i += blockDim.x) {
        int c = i >> 4;
        float su = gu[c] * rsqrtf(vu[c] + BN_EPS);
        d_wupf[i] = su * w_up[i];
    }
    for (int c = tid; c < NC; c += blockDim.x) {
        float su = gu[c] * rsqrtf(vu[c] + BN_EPS);
        d_bupf[c] = su * b_up[c] + (beu[c] - mu[c] * su);
    }
}

// ---------------- KNN: warp per row, per-thread top-20 + warp merge ----------------
__global__ void __launch_bounds__(256) knn_kernel(const float* __restrict__ xyz)
{
    __shared__ float sx[NPT];
    __shared__ float sy[NPT];
    __shared__ float sz[NPT];
    int b = blockIdx.y;
    const float* base = xyz + b * 3 * NPT;
    for (int i = threadIdx.x; i < NPT; i += 256) {
        sx[i] = base[i];
        sy[i] = base[NPT + i];
        sz[i] = base[2 * NPT + i];
    }
    __syncthreads();

    int warp = threadIdx.x >> 5;
    int lane = threadIdx.x & 31;
    int n = blockIdx.x * 8 + warp;
    float xn = sx[n], yn = sy[n], zn = sz[n];

    float bd[KK];
    int   bj[KK];
    #pragma unroll
    for (int i = 0; i < KK; ++i) { bd[i] = 1e30f; bj[i] = 0; }
    float worst = 1e30f;

    for (int j = lane; j < NPT; j += 32) {
        float dx = sx[j] - xn;
        float dy = sy[j] - yn;
        float dz = sz[j] - zn;
        float d = fmaf(dx, dx, fmaf(dy, dy, dz * dz));
        if (d < worst) {
            int p = KK - 1;
            while (p > 0 && bd[p - 1] > d) {
                bd[p] = bd[p - 1]; bj[p] = bj[p - 1]; --p;
            }
            bd[p] = d; bj[p] = j;
            worst = bd[KK - 1];
        }
    }

    // warp merge of 32 sorted lists -> global top-20
    int ptr = 0;
    int out_base = (b * NPT + n) * KK;
    for (int r = 0; r < KK; ++r) {
        float v = (ptr < KK) ? bd[ptr] : 1e30f;
        float mv = v; int ml = lane;
        #pragma unroll
        for (int off = 16; off > 0; off >>= 1) {
            float ov = __shfl_down_sync(0xffffffffu, mv, off);
            int   ol = __shfl_down_sync(0xffffffffu, ml, off);
            if (ov < mv) { mv = ov; ml = ol; }
        }
        ml = __shfl_sync(0xffffffffu, ml, 0);
        int cj = bj[(ptr < KK) ? ptr : (KK - 1)];
        int wj = __shfl_sync(0xffffffffu, cj, ml);
        if (lane == 0) d_idx[out_base + r] = wj;
        if (lane == ml) ptr++;
    }
}

// ---------------- PQ: per-point projections (feat 128->64 for P and Q, plus xyz MLP) ----
__global__ void __launch_bounds__(128) pq_kernel(const float* __restrict__ xyz,
                                                 const float* __restrict__ features)
{
    __shared__ __align__(16) float s_f[NC * 16];  // [j][p]
    __shared__ float s_w[64 * 129];               // [j_local][cout] padded
    __shared__ float s_x[3 * 16];                 // [j][p]
    int b = blockIdx.y;
    int n0 = blockIdx.x * 16;
    int tid = threadIdx.x;

    for (int i = tid; i < NC * 16; i += 128) {
        int j = i >> 4, p = i & 15;
        s_f[i] = features[b * NC * NPT + j * NPT + n0 + p];
    }
    if (tid < 48) {
        int j = tid >> 4, p = tid & 15;
        s_x[tid] = xyz[b * 3 * NPT + j * NPT + n0 + p];
    }

    float acc[16];
    #pragma unroll
    for (int p = 0; p < 16; ++p) acc[p] = 0.f;
    int cout = tid;

    for (int jc = 0; jc < NC; jc += 64) {
        __syncthreads();
        for (int i = tid; i < 64 * 128; i += 128) {
            int jl = i & 63, co = i >> 6;
            float w = (co < 64) ? d_w2p[co * NC + jc + jl]
                                : d_w2q[(co - 64) * NC + jc + jl];
            s_w[jl * 129 + co] = w;
        }
        __syncthreads();
        #pragma unroll 4
        for (int jl = 0; jl < 64; ++jl) {
            float w = s_w[jl * 129 + cout];
            const float4* f4 = (const float4*)(s_f + (jc + jl) * 16);
            float fv[16];
            *(float4*)(fv + 0)  = f4[0];
            *(float4*)(fv + 4)  = f4[1];
            *(float4*)(fv + 8)  = f4[2];
            *(float4*)(fv + 12) = f4[3];
            #pragma unroll
            for (int p = 0; p < 16; ++p) acc[p] = fmaf(w, fv[p], acc[p]);
        }
    }

    if (cout < 64) {
        #pragma unroll
        for (int p = 0; p < 16; ++p)
            d_P[(b * NPT + n0 + p) * NC + 64 + cout] = acc[p];
        float w0 = d_w1p[cout * 3], w1 = d_w1p[cout * 3 + 1], w2 = d_w1p[cout * 3 + 2];
        #pragma unroll
        for (int p = 0; p < 16; ++p)
            d_P[(b * NPT + n0 + p) * NC + cout] =
                fmaf(w0, s_x[p], fmaf(w1, s_x[16 + p], w2 * s_x[32 + p]));
    } else {
        int cq = cout - 64;
        float bb = d_b2f[cq];
        #pragma unroll
        for (int p = 0; p < 16; ++p)
            d_Q[(b * NPT + n0 + p) * NC + 64 + cq] = acc[p] + bb;
        float w0 = d_w1q[cq * 3], w1 = d_w1q[cq * 3 + 1], w2 = d_w1q[cq * 3 + 2];
        float b1 = d_b1f[cq];
        #pragma unroll
        for (int p = 0; p < 16; ++p)
            d_Q[(b * NPT + n0 + p) * NC + cq] =
                fmaf(w0, s_x[p], fmaf(w1, s_x[16 + p], fmaf(w2, s_x[32 + p], b1)));
    }
}

// ---------------- f_enc: gather neighbors' P, max, add Q, relu ----------------
__global__ void __launch_bounds__(128) fenc_kernel()
{
    __shared__ int s_idx[8 * KK];
    int b = blockIdx.y, n0 = blockIdx.x * 8, tid = threadIdx.x;
    for (int i = tid; i < 8 * KK; i += 128)
        s_idx[i] = d_idx[(b * NPT + n0) * KK + i];
    __syncthreads();
    const float* Pb = d_P + b * NPT * NC;
    for (int p = 0; p < 8; ++p) {
        int n = n0 + p;
        float q = d_Q[(b * NPT + n) * NC + tid];
        float m = -1e30f;
        #pragma unroll
        for (int k = 0; k < KK; ++k) {
            int j = s_idx[p * KK + k];
            m = fmaxf(m, Pb[j * NC + tid]);
        }
        d_fenc[(b * NPT + n) * NC + tid] = fmaxf(q + m, 0.f);
    }
}

// ---------------- down-proj f1/f2 + f_space + f_channel partials ----------------
__global__ void __launch_bounds__(256) down_kernel(const float* __restrict__ wd1,
                                                   const float* __restrict__ wd2)
{
    __shared__ float s_fe[8 * NC];
    __shared__ float s_w[32 * 129];
    __shared__ float s_part[CDD * 9];
    int b = blockIdx.y, n0 = blockIdx.x * 8, tid = threadIdx.x;

    for (int i = tid; i < 32 * NC; i += 256) {
        int o = i >> 7, c = i & 127;
        float w = (o < 16) ? wd1[o * NC + c] : wd2[(o - 16) * NC + c];
        s_w[o * 129 + c] = w;
    }
    for (int i = tid; i < 8 * NC; i += 256)
        s_fe[i] = d_fenc[(b * NPT + n0) * NC + i];
    __syncthreads();

    int o = tid & 31, p = tid >> 5;
    const float* wr = s_w + o * 129;
    const float* fr = s_fe + p * NC;
    float a = 0.f;
    #pragma unroll 8
    for (int c = 0; c < NC; ++c) a = fmaf(wr[c], fr[c], a);
    a = fmaxf(a, 0.f);
    int n = n0 + p;
    if (o < 16) {
        d_f1[(b * NPT + n) * CDD + o] = a;
        if (b == 0) s_part[o * 9 + p] = a;
    } else {
        d_f2[(b * NPT + n) * CDD + (o - 16)] = a;
    }
    if (b == 0) {
        float v = (o >= 16) ? a : 0.f;
        #pragma unroll
        for (int off = 16; off > 0; off >>= 1)
            v += __shfl_down_sync(0xffffffffu, v, off);
        if (o == 0) d_fsp[n] = v * (1.f / 16.f);
        __syncthreads();
        if (tid < CDD) {
            float s = 0.f;
            #pragma unroll
            for (int p2 = 0; p2 < 8; ++p2) s += s_part[tid * 9 + p2];
            d_fchpart[blockIdx.x * CDD + tid] = s;
        }
    }
}

// ---------------- deterministic f_channel reduction ----------------
__global__ void fch_kernel()
{
    int o = threadIdx.x;
    float s = 0.f;
    for (int blk = 0; blk < 512; ++blk) s += d_fchpart[blk * CDD + o];
    d_fch[o] = s * (1.f / (float)NPT);
}

// ---------------- final: attention cross-term, up-proj+BN+relu, mish, transpose-store --
__global__ void __launch_bounds__(256) final_kernel(float* __restrict__ out)
{
    __shared__ float s_v[16 * 33];
    __shared__ float s_o[128 * 33];
    int b = blockIdx.y, n0 = blockIdx.x * 32, tid = threadIdx.x;

    for (int i = tid; i < 512; i += 256) {
        int o = i & 15, p = i >> 4;
        int n = n0 + p;
        float f1v = d_f1[(b * NPT + n) * CDD + o];
        float f2v = d_f2[(b * NPT + n) * CDD + o];
        float cross = sqrtf(fmaf(d_fch[o], d_fsp[n], 1e-12f));
        s_v[o * 33 + p] = cross + f1v + f2v;
    }
    __syncthreads();

    int c = tid & 127, ph = tid >> 7;
    float w16[16];
    #pragma unroll
    for (int o = 0; o < 16; ++o) w16[o] = d_wupf[c * CDD + o];
    float bup = d_bupf[c];

    for (int p = ph * 16; p < ph * 16 + 16; ++p) {
        float a = bup;
        #pragma unroll
        for (int o = 0; o < 16; ++o) a = fmaf(w16[o], s_v[o * 33 + p], a);
        float U = fmaxf(a, 0.f);
        float fe = d_fenc[(b * NPT + n0 + p) * NC + c];
        float x = fe - U;
        float sp = fmaxf(x, 0.f) + log1pf(expf(-fabsf(x)));
        s_o[c * 33 + p] = x * tanhf(sp);
    }
    __syncthreads();

    for (int i = tid; i < 128 * 32; i += 256) {
        int cc = i >> 5, p = i & 31;
        out[b * NC * NPT + cc * NPT + n0 + p] = s_o[cc * 33 + p];
    }
}

// ---------------- launch ----------------
extern "C" void kernel_launch(void* const* d_in, const int* in_sizes, int n_in,
                              void* d_out, int out_size)
{
    const float* xyz      = (const float*)d_in[0];
    const float* features = (const float*)d_in[1];
    const float* w_mlp1   = (const float*)d_in[2];
    const float* b_mlp1   = (const float*)d_in[3];
    const float* g1       = (const float*)d_in[4];
    const float* be1      = (const float*)d_in[5];
    const float* m1       = (const float*)d_in[6];
    const float* v1       = (const float*)d_in[7];
    const float* w_mlp2   = (const float*)d_in[8];
    const float* b_mlp2   = (const float*)d_in[9];
    const float* g2       = (const float*)d_in[10];
    const float* be2      = (const float*)d_in[11];
    const float* m2       = (const float*)d_in[12];
    const float* v2       = (const float*)d_in[13];
    const float* w_down1  = (const float*)d_in[14];
    const float* w_down2  = (const float*)d_in[15];
    const float* w_up     = (const float*)d_in[16];
    const float* b_up     = (const float*)d_in[17];
    const float* gu       = (const float*)d_in[18];
    const float* beu      = (const float*)d_in[19];
    const float* mu       = (const float*)d_in[20];
    const float* vu       = (const float*)d_in[21];
    // d_in[22] = k (always 20 for this problem; compiled in)

    prep_kernel<<<1, 256>>>(w_mlp1, b_mlp1, g1, be1, m1, v1,
                            w_mlp2, b_mlp2, g2, be2, m2, v2,
                            w_up, b_up, gu, beu, mu, vu);
    knn_kernel<<<dim3(NPT / 8, NB), 256>>>(xyz);
    pq_kernel<<<dim3(NPT / 16, NB), 128>>>(xyz, features);
    fenc_kernel<<<dim3(NPT / 8, NB), 128>>>();
    down_kernel<<<dim3(NPT / 8, NB), 256>>>(w_down1, w_down2);
    fch_kernel<<<1, CDD>>>();
    final_kernel<<<dim3(NPT / 32, NB), 256>>>((float*)d_out);
}

// round 8
// speedup vs baseline: 6.3620x; 6.3482x over previous
#include <cuda_runtime.h>
#include <math.h>

#define BN_EPS 1e-5f
#define NB 2
#define NC 128
#define NPT 4096
#define KK 20
#define CHH 64
#define CDD 16

// ---------------- device scratch (no allocations allowed) ----------------
__device__ int   d_idx[NB * NPT * KK];
__device__ float d_P[NB * NPT * NC];       // [b][n][c]  c<64: xyz-half, c>=64: feat-half
__device__ float d_Q[NB * NPT * NC];
__device__ float d_fenc[NB * NPT * NC];    // [b][n][c]
__device__ float d_f1[NB * NPT * CDD];     // [b][n][o]
__device__ float d_f2[NB * NPT * CDD];
__device__ float d_fsp[NPT];
__device__ float d_fch[CDD];
__device__ float d_fchpart[512 * CDD];
// folded weights
__device__ float d_w1p[CHH * 3], d_w1q[CHH * 3], d_b1f[CHH];
__device__ float d_w2p[CHH * NC], d_w2q[CHH * NC], d_b2f[CHH];
__device__ float d_wupf[NC * CDD], d_bupf[NC];

// ---------------- prep: fold BN + split weights ----------------
__global__ void prep_kernel(const float* w_mlp1, const float* b_mlp1,
                            const float* g1, const float* be1, const float* m1, const float* v1,
                            const float* w_mlp2, const float* b_mlp2,
                            const float* g2, const float* be2, const float* m2, const float* v2,
                            const float* w_up, const float* b_up,
                            const float* gu, const float* beu, const float* mu, const float* vu)
{
    int tid = threadIdx.x;
    for (int c = tid; c < CHH; c += blockDim.x) {
        float s = g1[c] * rsqrtf(v1[c] + BN_EPS);
        float t = be1[c] - m1[c] * s;
        d_b1f[c] = s * b_mlp1[c] + t;
        #pragma unroll
        for (int j = 0; j < 3; ++j) {
            float wx = w_mlp1[c * 6 + j];
            float wc = w_mlp1[c * 6 + 3 + j];
            d_w1p[c * 3 + j] = s * wx;
            d_w1q[c * 3 + j] = s * (wc - wx);
        }
        float s2 = g2[c] * rsqrtf(v2[c] + BN_EPS);
        float t2 = be2[c] - m2[c] * s2;
        d_b2f[c] = s2 * b_mlp2[c] + t2;
    }
    for (int i = tid; i < CHH * NC; i += blockDim.x) {
        int c = i >> 7;
        float s2 = g2[c] * rsqrtf(v2[c] + BN_EPS);
        int j = i & 127;
        float wa = w_mlp2[c * 256 + j];
        float wb = w_mlp2[c * 256 + 128 + j];
        d_w2p[i] = s2 * wa;
        d_w2q[i] = s2 * (wb - wa);
    }
    for (int i = tid; i < NC * CDD; i += blockDim.x) {
        int c = i >> 4;
        float su = gu[c] * rsqrtf(vu[c] + BN_EPS);
        d_wupf[i] = su * w_up[i];
    }
    for (int c = tid; c < NC; c += blockDim.x) {
        float su = gu[c] * rsqrtf(vu[c] + BN_EPS);
        d_bupf[c] = su * b_up[c] + (beu[c] - mu[c] * su);
    }
}

// ---------------- KNN: warp per row, REGISTER-resident top-20 ----------------
// Key change vs previous round: no dynamic indexing into bd[]/bj[] anywhere.
// Candidate phase uses a fully-unrolled predicated bubble insert (registers).
// Merge phase dumps per-lane sorted lists to smem (reusing the point-cloud
// union) and only the winning lane does one LDS per round to advance its head.
__global__ void __launch_bounds__(256) knn_kernel(const float* __restrict__ xyz)
{
    __shared__ union {
        struct { float x[NPT]; float y[NPT]; float z[NPT]; } p;      // 48KB
        struct { float md[8 * KK * 32]; int mi[8 * KK * 32]; } m;    // 40KB
    } sh;

    int b = blockIdx.y;
    const float* base = xyz + b * 3 * NPT;
    for (int i = threadIdx.x; i < NPT; i += 256) {
        sh.p.x[i] = base[i];
        sh.p.y[i] = base[NPT + i];
        sh.p.z[i] = base[2 * NPT + i];
    }
    __syncthreads();

    int warp = threadIdx.x >> 5;
    int lane = threadIdx.x & 31;
    int n = blockIdx.x * 8 + warp;
    float xn = sh.p.x[n], yn = sh.p.y[n], zn = sh.p.z[n];

    float bd[KK];
    int   bj[KK];
    #pragma unroll
    for (int i = 0; i < KK; ++i) { bd[i] = 1e30f; bj[i] = 0; }

    for (int j = lane; j < NPT; j += 32) {
        float dx = sh.p.x[j] - xn;
        float dy = sh.p.y[j] - yn;
        float dz = sh.p.z[j] - zn;
        float d = fmaf(dx, dx, fmaf(dy, dy, dz * dz));
        if (d < bd[KK - 1]) {
            bd[KK - 1] = d;
            bj[KK - 1] = j;
            // one bubble pass with static indices -> stays in registers
            #pragma unroll
            for (int i = KK - 1; i > 0; --i) {
                bool sw = bd[i] < bd[i - 1];
                float td = bd[i - 1]; int tj = bj[i - 1];
                if (sw) {
                    bd[i - 1] = bd[i]; bj[i - 1] = bj[i];
                    bd[i] = td;        bj[i] = tj;
                }
            }
        }
    }

    // all warps must be done reading the point cloud before we reuse the smem
    __syncthreads();

    // dump lists: layout [warp][elem][lane] -> conflict-free per-lane reads
    #pragma unroll
    for (int i = 0; i < KK; ++i) {
        sh.m.md[(warp * KK + i) * 32 + lane] = bd[i];
        sh.m.mi[(warp * KK + i) * 32 + lane] = bj[i];
    }

    // warp merge of 32 sorted lists -> global top-20 (same ordering semantics
    // as the previous passing version: strict <, reduce-tree lane tie-break)
    int   ptr = 0;
    float head = bd[0];
    int   headj = bj[0];
    int out_base = (b * NPT + n) * KK;
    for (int r = 0; r < KK; ++r) {
        float mv = head; int ml = lane;
        #pragma unroll
        for (int off = 16; off > 0; off >>= 1) {
            float ov = __shfl_down_sync(0xffffffffu, mv, off);
            int   ol = __shfl_down_sync(0xffffffffu, ml, off);
            if (ov < mv) { mv = ov; ml = ol; }
        }
        ml = __shfl_sync(0xffffffffu, ml, 0);
        int wj = __shfl_sync(0xffffffffu, headj, ml);
        if (lane == 0) d_idx[out_base + r] = wj;
        if (lane == ml) {
            ptr++;
            int pi = (ptr < KK) ? ptr : (KK - 1);
            head  = sh.m.md[(warp * KK + pi) * 32 + lane];
            headj = sh.m.mi[(warp * KK + pi) * 32 + lane];
            if (ptr >= KK) head = 1e30f;
        }
    }
}

// ---------------- PQ: per-point projections (feat 128->64 for P and Q, plus xyz MLP) ----
__global__ void __launch_bounds__(128) pq_kernel(const float* __restrict__ xyz,
                                                 const float* __restrict__ features)
{
    __shared__ __align__(16) float s_f[NC * 16];  // [j][p]
    __shared__ float s_w[64 * 129];               // [j_local][cout] padded
    __shared__ float s_x[3 * 16];                 // [j][p]
    int b = blockIdx.y;
    int n0 = blockIdx.x * 16;
    int tid = threadIdx.x;

    for (int i = tid; i < NC * 16; i += 128) {
        int j = i >> 4, p = i & 15;
        s_f[i] = features[b * NC * NPT + j * NPT + n0 + p];
    }
    if (tid < 48) {
        int j = tid >> 4, p = tid & 15;
        s_x[tid] = xyz[b * 3 * NPT + j * NPT + n0 + p];
    }

    float acc[16];
    #pragma unroll
    for (int p = 0; p < 16; ++p) acc[p] = 0.f;
    int cout = tid;

    for (int jc = 0; jc < NC; jc += 64) {
        __syncthreads();
        for (int i = tid; i < 64 * 128; i += 128) {
            int jl = i & 63, co = i >> 6;
            float w = (co < 64) ? d_w2p[co * NC + jc + jl]
                                : d_w2q[(co - 64) * NC + jc + jl];
            s_w[jl * 129 + co] = w;
        }
        __syncthreads();
        #pragma unroll 4
        for (int jl = 0; jl < 64; ++jl) {
            float w = s_w[jl * 129 + cout];
            const float4* f4 = (const float4*)(s_f + (jc + jl) * 16);
            float fv[16];
            *(float4*)(fv + 0)  = f4[0];
            *(float4*)(fv + 4)  = f4[1];
            *(float4*)(fv + 8)  = f4[2];
            *(float4*)(fv + 12) = f4[3];
            #pragma unroll
            for (int p = 0; p < 16; ++p) acc[p] = fmaf(w, fv[p], acc[p]);
        }
    }

    if (cout < 64) {
        #pragma unroll
        for (int p = 0; p < 16; ++p)
            d_P[(b * NPT + n0 + p) * NC + 64 + cout] = acc[p];
        float w0 = d_w1p[cout * 3], w1 = d_w1p[cout * 3 + 1], w2 = d_w1p[cout * 3 + 2];
        #pragma unroll
        for (int p = 0; p < 16; ++p)
            d_P[(b * NPT + n0 + p) * NC + cout] =
                fmaf(w0, s_x[p], fmaf(w1, s_x[16 + p], w2 * s_x[32 + p]));
    } else {
        int cq = cout - 64;
        float bb = d_b2f[cq];
        #pragma unroll
        for (int p = 0; p < 16; ++p)
            d_Q[(b * NPT + n0 + p) * NC + 64 + cq] = acc[p] + bb;
        float w0 = d_w1q[cq * 3], w1 = d_w1q[cq * 3 + 1], w2 = d_w1q[cq * 3 + 2];
        float b1 = d_b1f[cq];
        #pragma unroll
        for (int p = 0; p < 16; ++p)
            d_Q[(b * NPT + n0 + p) * NC + cq] =
                fmaf(w0, s_x[p], fmaf(w1, s_x[16 + p], fmaf(w2, s_x[32 + p], b1)));
    }
}

// ---------------- f_enc: gather neighbors' P, max, add Q, relu ----------------
__global__ void __launch_bounds__(128) fenc_kernel()
{
    __shared__ int s_idx[8 * KK];
    int b = blockIdx.y, n0 = blockIdx.x * 8, tid = threadIdx.x;
    for (int i = tid; i < 8 * KK; i += 128)
        s_idx[i] = d_idx[(b * NPT + n0) * KK + i];
    __syncthreads();
    const float* Pb = d_P + b * NPT * NC;
    for (int p = 0; p < 8; ++p) {
        int n = n0 + p;
        float q = d_Q[(b * NPT + n) * NC + tid];
        float m = -1e30f;
        #pragma unroll
        for (int k = 0; k < KK; ++k) {
            int j = s_idx[p * KK + k];
            m = fmaxf(m, Pb[j * NC + tid]);
        }
        d_fenc[(b * NPT + n) * NC + tid] = fmaxf(q + m, 0.f);
    }
}

// ---------------- down-proj f1/f2 + f_space + f_channel partials ----------------
__global__ void __launch_bounds__(256) down_kernel(const float* __restrict__ wd1,
                                                   const float* __restrict__ wd2)
{
    __shared__ float s_fe[8 * NC];
    __shared__ float s_w[32 * 129];
    __shared__ float s_part[CDD * 9];
    int b = blockIdx.y, n0 = blockIdx.x * 8, tid = threadIdx.x;

    for (int i = tid; i < 32 * NC; i += 256) {
        int o = i >> 7, c = i & 127;
        float w = (o < 16) ? wd1[o * NC + c] : wd2[(o - 16) * NC + c];
        s_w[o * 129 + c] = w;
    }
    for (int i = tid; i < 8 * NC; i += 256)
        s_fe[i] = d_fenc[(b * NPT + n0) * NC + i];
    __syncthreads();

    int o = tid & 31, p = tid >> 5;
    const float* wr = s_w + o * 129;
    const float* fr = s_fe + p * NC;
    float a = 0.f;
    #pragma unroll 8
    for (int c = 0; c < NC; ++c) a = fmaf(wr[c], fr[c], a);
    a = fmaxf(a, 0.f);
    int n = n0 + p;
    if (o < 16) {
        d_f1[(b * NPT + n) * CDD + o] = a;
        if (b == 0) s_part[o * 9 + p] = a;
    } else {
        d_f2[(b * NPT + n) * CDD + (o - 16)] = a;
    }
    if (b == 0) {
        float v = (o >= 16) ? a : 0.f;
        #pragma unroll
        for (int off = 16; off > 0; off >>= 1)
            v += __shfl_down_sync(0xffffffffu, v, off);
        if (o == 0) d_fsp[n] = v * (1.f / 16.f);
        __syncthreads();
        if (tid < CDD) {
            float s = 0.f;
            #pragma unroll
            for (int p2 = 0; p2 < 8; ++p2) s += s_part[tid * 9 + p2];
            d_fchpart[blockIdx.x * CDD + tid] = s;
        }
    }
}

// ---------------- deterministic f_channel reduction ----------------
__global__ void fch_kernel()
{
    int o = threadIdx.x;
    float s = 0.f;
    for (int blk = 0; blk < 512; ++blk) s += d_fchpart[blk * CDD + o];
    d_fch[o] = s * (1.f / (float)NPT);
}

// ---------------- final: attention cross-term, up-proj+BN+relu, mish, transpose-store --
__global__ void __launch_bounds__(256) final_kernel(float* __restrict__ out)
{
    __shared__ float s_v[16 * 33];
    __shared__ float s_o[128 * 33];
    int b = blockIdx.y, n0 = blockIdx.x * 32, tid = threadIdx.x;

    for (int i = tid; i < 512; i += 256) {
        int o = i & 15, p = i >> 4;
        int n = n0 + p;
        float f1v = d_f1[(b * NPT + n) * CDD + o];
        float f2v = d_f2[(b * NPT + n) * CDD + o];
        float cross = sqrtf(fmaf(d_fch[o], d_fsp[n], 1e-12f));
        s_v[o * 33 + p] = cross + f1v + f2v;
    }
    __syncthreads();

    int c = tid & 127, ph = tid >> 7;
    float w16[16];
    #pragma unroll
    for (int o = 0; o < 16; ++o) w16[o] = d_wupf[c * CDD + o];
    float bup = d_bupf[c];

    for (int p = ph * 16; p < ph * 16 + 16; ++p) {
        float a = bup;
        #pragma unroll
        for (int o = 0; o < 16; ++o) a = fmaf(w16[o], s_v[o * 33 + p], a);
        float U = fmaxf(a, 0.f);
        float fe = d_fenc[(b * NPT + n0 + p) * NC + c];
        float x = fe - U;
        float sp = fmaxf(x, 0.f) + log1pf(expf(-fabsf(x)));
        s_o[c * 33 + p] = x * tanhf(sp);
    }
    __syncthreads();

    for (int i = tid; i < 128 * 32; i += 256) {
        int cc = i >> 5, p = i & 31;
        out[b * NC * NPT + cc * NPT + n0 + p] = s_o[cc * 33 + p];
    }
}

// ---------------- launch ----------------
extern "C" void kernel_launch(void* const* d_in, const int* in_sizes, int n_in,
                              void* d_out, int out_size)
{
    const float* xyz      = (const float*)d_in[0];
    const float* features = (const float*)d_in[1];
    const float* w_mlp1   = (const float*)d_in[2];
    const float* b_mlp1   = (const float*)d_in[3];
    const float* g1       = (const float*)d_in[4];
    const float* be1      = (const float*)d_in[5];
    const float* m1       = (const float*)d_in[6];
    const float* v1       = (const float*)d_in[7];
    const float* w_mlp2   = (const float*)d_in[8];
    const float* b_mlp2   = (const float*)d_in[9];
    const float* g2       = (const float*)d_in[10];
    const float* be2      = (const float*)d_in[11];
    const float* m2       = (const float*)d_in[12];
    const float* v2       = (const float*)d_in[13];
    const float* w_down1  = (const float*)d_in[14];
    const float* w_down2  = (const float*)d_in[15];
    const float* w_up     = (const float*)d_in[16];
    const float* b_up     = (const float*)d_in[17];
    const float* gu       = (const float*)d_in[18];
    const float* beu      = (const float*)d_in[19];
    const float* mu       = (const float*)d_in[20];
    const float* vu       = (const float*)d_in[21];
    // d_in[22] = k (always 20 for this problem; compiled in)

    prep_kernel<<<1, 256>>>(w_mlp1, b_mlp1, g1, be1, m1, v1,
                            w_mlp2, b_mlp2, g2, be2, m2, v2,
                            w_up, b_up, gu, beu, mu, vu);
    knn_kernel<<<dim3(NPT / 8, NB), 256>>>(xyz);
    pq_kernel<<<dim3(NPT / 16, NB), 128>>>(xyz, features);
    fenc_kernel<<<dim3(NPT / 8, NB), 128>>>();
    down_kernel<<<dim3(NPT / 8, NB), 256>>>(w_down1, w_down2);
    fch_kernel<<<1, CDD>>>();
    final_kernel<<<dim3(NPT / 32, NB), 256>>>((float*)d_out);
}

// round 9
// speedup vs baseline: 6.3891x; 1.0043x over previous
#include <cuda_runtime.h>
#include <math.h>

#define BN_EPS 1e-5f
#define NB 2
#define NC 128
#define NPT 4096
#define KK 20
#define CHH 64
#define CDD 16

// ---------------- device scratch (no allocations allowed) ----------------
__device__ int   d_idx[NB * NPT * KK];
__device__ float d_P[NB * NPT * NC];       // [b][n][c]  c<64: xyz-half, c>=64: feat-half
__device__ float d_Q[NB * NPT * NC];
__device__ float d_fenc[NB * NPT * NC];    // [b][n][c]
__device__ float d_f1[NB * NPT * CDD];     // [b][n][o]
__device__ float d_f2[NB * NPT * CDD];
__device__ float d_fsp[NPT];
__device__ float d_fch[CDD];
__device__ float d_fchpart[512 * CDD];
// folded weights
__device__ float d_w1p[CHH * 3], d_w1q[CHH * 3], d_b1f[CHH];
__device__ float d_w2p[CHH * NC], d_w2q[CHH * NC], d_b2f[CHH];
__device__ float d_wupf[NC * CDD], d_bupf[NC];

// ---------------- prep: fold BN + split weights ----------------
__global__ void prep_kernel(const float* w_mlp1, const float* b_mlp1,
                            const float* g1, const float* be1, const float* m1, const float* v1,
                            const float* w_mlp2, const float* b_mlp2,
                            const float* g2, const float* be2, const float* m2, const float* v2,
                            const float* w_up, const float* b_up,
                            const float* gu, const float* beu, const float* mu, const float* vu)
{
    int tid = threadIdx.x;
    for (int c = tid; c < CHH; c += blockDim.x) {
        float s = g1[c] * rsqrtf(v1[c] + BN_EPS);
        float t = be1[c] - m1[c] * s;
        d_b1f[c] = s * b_mlp1[c] + t;
        #pragma unroll
        for (int j = 0; j < 3; ++j) {
            float wx = w_mlp1[c * 6 + j];
            float wc = w_mlp1[c * 6 + 3 + j];
            d_w1p[c * 3 + j] = s * wx;
            d_w1q[c * 3 + j] = s * (wc - wx);
        }
        float s2 = g2[c] * rsqrtf(v2[c] + BN_EPS);
        float t2 = be2[c] - m2[c] * s2;
        d_b2f[c] = s2 * b_mlp2[c] + t2;
    }
    for (int i = tid; i < CHH * NC; i += blockDim.x) {
        int c = i >> 7;
        float s2 = g2[c] * rsqrtf(v2[c] + BN_EPS);
        int j = i & 127;
        float wa = w_mlp2[c * 256 + j];
        float wb = w_mlp2[c * 256 + 128 + j];
        d_w2p[i] = s2 * wa;
        d_w2q[i] = s2 * (wb - wa);
    }
    for (int i = tid; i < NC * CDD; i += blockDim.x) {
        int c = i >> 4;
        float su = gu[c] * rsqrtf(vu[c] + BN_EPS);
        d_wupf[i] = su * w_up[i];
    }
    for (int c = tid; c < NC; c += blockDim.x) {
        float su = gu[c] * rsqrtf(vu[c] + BN_EPS);
        d_bupf[c] = su * b_up[c] + (beu[c] - mu[c] * su);
    }
}

// ---------------- KNN: warp per row, REGISTER-resident top-20 ----------------
// Key change vs previous round: no dynamic indexing into bd[]/bj[] anywhere.
// Candidate phase uses a fully-unrolled predicated bubble insert (registers).
// Merge phase dumps per-lane sorted lists to smem (reusing the point-cloud
// union) and only the winning lane does one LDS per round to advance its head.
__global__ void __launch_bounds__(256) knn_kernel(const float* __restrict__ xyz)
{
    __shared__ union {
        struct { float x[NPT]; float y[NPT]; float z[NPT]; } p;      // 48KB
        struct { float md[8 * KK * 32]; int mi[8 * KK * 32]; } m;    // 40KB
    } sh;

    int b = blockIdx.y;
    const float* base = xyz + b * 3 * NPT;
    for (int i = threadIdx.x; i < NPT; i += 256) {
        sh.p.x[i] = base[i];
        sh.p.y[i] = base[NPT + i];
        sh.p.z[i] = base[2 * NPT + i];
    }
    __syncthreads();

    int warp = threadIdx.x >> 5;
    int lane = threadIdx.x & 31;
    int n = blockIdx.x * 8 + warp;
    float xn = sh.p.x[n], yn = sh.p.y[n], zn = sh.p.z[n];

    float bd[KK];
    int   bj[KK];
    #pragma unroll
    for (int i = 0; i < KK; ++i) { bd[i] = 1e30f; bj[i] = 0; }

    for (int j = lane; j < NPT; j += 32) {
        float dx = sh.p.x[j] - xn;
        float dy = sh.p.y[j] - yn;
        float dz = sh.p.z[j] - zn;
        float d = fmaf(dx, dx, fmaf(dy, dy, dz * dz));
        if (d < bd[KK - 1]) {
            bd[KK - 1] = d;
            bj[KK - 1] = j;
            // one bubble pass with static indices -> stays in registers
            #pragma unroll
            for (int i = KK - 1; i > 0; --i) {
                bool sw = bd[i] < bd[i - 1];
                float td = bd[i - 1]; int tj = bj[i - 1];
                if (sw) {
                    bd[i - 1] = bd[i]; bj[i - 1] = bj[i];
                    bd[i] = td;        bj[i] = tj;
                }
            }
        }
    }

    // all warps must be done reading the point cloud before we reuse the smem
    __syncthreads();

    // dump lists: layout [warp][elem][lane] -> conflict-free per-lane reads
    #pragma unroll
    for (int i = 0; i < KK; ++i) {
        sh.m.md[(warp * KK + i) * 32 + lane] = bd[i];
        sh.m.mi[(warp * KK + i) * 32 + lane] = bj[i];
    }

    // warp merge of 32 sorted lists -> global top-20 (same ordering semantics
    // as the previous passing version: strict <, reduce-tree lane tie-break)
    int   ptr = 0;
    float head = bd[0];
    int   headj = bj[0];
    int out_base = (b * NPT + n) * KK;
    for (int r = 0; r < KK; ++r) {
        float mv = head; int ml = lane;
        #pragma unroll
        for (int off = 16; off > 0; off >>= 1) {
            float ov = __shfl_down_sync(0xffffffffu, mv, off);
            int   ol = __shfl_down_sync(0xffffffffu, ml, off);
            if (ov < mv) { mv = ov; ml = ol; }
        }
        ml = __shfl_sync(0xffffffffu, ml, 0);
        int wj = __shfl_sync(0xffffffffu, headj, ml);
        if (lane == 0) d_idx[out_base + r] = wj;
        if (lane == ml) {
            ptr++;
            int pi = (ptr < KK) ? ptr : (KK - 1);
            head  = sh.m.md[(warp * KK + pi) * 32 + lane];
            headj = sh.m.mi[(warp * KK + pi) * 32 + lane];
            if (ptr >= KK) head = 1e30f;
        }
    }
}

// ---------------- PQ: per-point projections (feat 128->64 for P and Q, plus xyz MLP) ----
__global__ void __launch_bounds__(128) pq_kernel(const float* __restrict__ xyz,
                                                 const float* __restrict__ features)
{
    __shared__ __align__(16) float s_f[NC * 16];  // [j][p]
    __shared__ float s_w[64 * 129];               // [j_local][cout] padded
    __shared__ float s_x[3 * 16];                 // [j][p]
    int b = blockIdx.y;
    int n0 = blockIdx.x * 16;
    int tid = threadIdx.x;

    for (int i = tid; i < NC * 16; i += 128) {
        int j = i >> 4, p = i & 15;
        s_f[i] = features[b * NC * NPT + j * NPT + n0 + p];
    }
    if (tid < 48) {
        int j = tid >> 4, p = tid & 15;
        s_x[tid] = xyz[b * 3 * NPT + j * NPT + n0 + p];
    }

    float acc[16];
    #pragma unroll
    for (int p = 0; p < 16; ++p) acc[p] = 0.f;
    int cout = tid;

    for (int jc = 0; jc < NC; jc += 64) {
        __syncthreads();
        for (int i = tid; i < 64 * 128; i += 128) {
            int jl = i & 63, co = i >> 6;
            float w = (co < 64) ? d_w2p[co * NC + jc + jl]
                                : d_w2q[(co - 64) * NC + jc + jl];
            s_w[jl * 129 + co] = w;
        }
        __syncthreads();
        #pragma unroll 4
        for (int jl = 0; jl < 64; ++jl) {
            float w = s_w[jl * 129 + cout];
            const float4* f4 = (const float4*)(s_f + (jc + jl) * 16);
            float fv[16];
            *(float4*)(fv + 0)  = f4[0];
            *(float4*)(fv + 4)  = f4[1];
            *(float4*)(fv + 8)  = f4[2];
            *(float4*)(fv + 12) = f4[3];
            #pragma unroll
            for (int p = 0; p < 16; ++p) acc[p] = fmaf(w, fv[p], acc[p]);
        }
    }

    if (cout < 64) {
        #pragma unroll
        for (int p = 0; p < 16; ++p)
            d_P[(b * NPT + n0 + p) * NC + 64 + cout] = acc[p];
        float w0 = d_w1p[cout * 3], w1 = d_w1p[cout * 3 + 1], w2 = d_w1p[cout * 3 + 2];
        #pragma unroll
        for (int p = 0; p < 16; ++p)
            d_P[(b * NPT + n0 + p) * NC + cout] =
                fmaf(w0, s_x[p], fmaf(w1, s_x[16 + p], w2 * s_x[32 + p]));
    } else {
        int cq = cout - 64;
        float bb = d_b2f[cq];
        #pragma unroll
        for (int p = 0; p < 16; ++p)
            d_Q[(b * NPT + n0 + p) * NC + 64 + cq] = acc[p] + bb;
        float w0 = d_w1q[cq * 3], w1 = d_w1q[cq * 3 + 1], w2 = d_w1q[cq * 3 + 2];
        float b1 = d_b1f[cq];
        #pragma unroll
        for (int p = 0; p < 16; ++p)
            d_Q[(b * NPT + n0 + p) * NC + cq] =
                fmaf(w0, s_x[p], fmaf(w1, s_x[16 + p], fmaf(w2, s_x[32 + p], b1)));
    }
}

// ---------------- f_enc: gather neighbors' P, max, add Q, relu ----------------
__global__ void __launch_bounds__(128) fenc_kernel()
{
    __shared__ int s_idx[8 * KK];
    int b = blockIdx.y, n0 = blockIdx.x * 8, tid = threadIdx.x;
    for (int i = tid; i < 8 * KK; i += 128)
        s_idx[i] = d_idx[(b * NPT + n0) * KK + i];
    __syncthreads();
    const float* Pb = d_P + b * NPT * NC;
    for (int p = 0; p < 8; ++p) {
        int n = n0 + p;
        float q = d_Q[(b * NPT + n) * NC + tid];
        float m = -1e30f;
        #pragma unroll
        for (int k = 0; k < KK; ++k) {
            int j = s_idx[p * KK + k];
            m = fmaxf(m, Pb[j * NC + tid]);
        }
        d_fenc[(b * NPT + n) * NC + tid] = fmaxf(q + m, 0.f);
    }
}

// ---------------- down-proj f1/f2 + f_space + f_channel partials ----------------
__global__ void __launch_bounds__(256) down_kernel(const float* __restrict__ wd1,
                                                   const float* __restrict__ wd2)
{
    __shared__ float s_fe[8 * NC];
    __shared__ float s_w[32 * 129];
    __shared__ float s_part[CDD * 9];
    int b = blockIdx.y, n0 = blockIdx.x * 8, tid = threadIdx.x;

    for (int i = tid; i < 32 * NC; i += 256) {
        int o = i >> 7, c = i & 127;
        float w = (o < 16) ? wd1[o * NC + c] : wd2[(o - 16) * NC + c];
        s_w[o * 129 + c] = w;
    }
    for (int i = tid; i < 8 * NC; i += 256)
        s_fe[i] = d_fenc[(b * NPT + n0) * NC + i];
    __syncthreads();

    int o = tid & 31, p = tid >> 5;
    const float* wr = s_w + o * 129;
    const float* fr = s_fe + p * NC;
    float a = 0.f;
    #pragma unroll 8
    for (int c = 0; c < NC; ++c) a = fmaf(wr[c], fr[c], a);
    a = fmaxf(a, 0.f);
    int n = n0 + p;
    if (o < 16) {
        d_f1[(b * NPT + n) * CDD + o] = a;
        if (b == 0) s_part[o * 9 + p] = a;
    } else {
        d_f2[(b * NPT + n) * CDD + (o - 16)] = a;
    }
    if (b == 0) {
        float v = (o >= 16) ? a : 0.f;
        #pragma unroll
        for (int off = 16; off > 0; off >>= 1)
            v += __shfl_down_sync(0xffffffffu, v, off);
        if (o == 0) d_fsp[n] = v * (1.f / 16.f);
        __syncthreads();
        if (tid < CDD) {
            float s = 0.f;
            #pragma unroll
            for (int p2 = 0; p2 < 8; ++p2) s += s_part[tid * 9 + p2];
            d_fchpart[blockIdx.x * CDD + tid] = s;
        }
    }
}

// ---------------- deterministic f_channel reduction ----------------
__global__ void fch_kernel()
{
    int o = threadIdx.x;
    float s = 0.f;
    for (int blk = 0; blk < 512; ++blk) s += d_fchpart[blk * CDD + o];
    d_fch[o] = s * (1.f / (float)NPT);
}

// ---------------- final: attention cross-term, up-proj+BN+relu, mish, transpose-store --
__global__ void __launch_bounds__(256) final_kernel(float* __restrict__ out)
{
    __shared__ float s_v[16 * 33];
    __shared__ float s_o[128 * 33];
    int b = blockIdx.y, n0 = blockIdx.x * 32, tid = threadIdx.x;

    for (int i = tid; i < 512; i += 256) {
        int o = i & 15, p = i >> 4;
        int n = n0 + p;
        float f1v = d_f1[(b * NPT + n) * CDD + o];
        float f2v = d_f2[(b * NPT + n) * CDD + o];
        float cross = sqrtf(fmaf(d_fch[o], d_fsp[n], 1e-12f));
        s_v[o * 33 + p] = cross + f1v + f2v;
    }
    __syncthreads();

    int c = tid & 127, ph = tid >> 7;
    float w16[16];
    #pragma unroll
    for (int o = 0; o < 16; ++o) w16[o] = d_wupf[c * CDD + o];
    float bup = d_bupf[c];

    for (int p = ph * 16; p < ph * 16 + 16; ++p) {
        float a = bup;
        #pragma unroll
        for (int o = 0; o < 16; ++o) a = fmaf(w16[o], s_v[o * 33 + p], a);
        float U = fmaxf(a, 0.f);
        float fe = d_fenc[(b * NPT + n0 + p) * NC + c];
        float x = fe - U;
        float sp = fmaxf(x, 0.f) + log1pf(expf(-fabsf(x)));
        s_o[c * 33 + p] = x * tanhf(sp);
    }
    __syncthreads();

    for (int i = tid; i < 128 * 32; i += 256) {
        int cc = i >> 5, p = i & 31;
        out[b * NC * NPT + cc * NPT + n0 + p] = s_o[cc * 33 + p];
    }
}

// ---------------- launch ----------------
extern "C" void kernel_launch(void* const* d_in, const int* in_sizes, int n_in,
                              void* d_out, int out_size)
{
    const float* xyz      = (const float*)d_in[0];
    const float* features = (const float*)d_in[1];
    const float* w_mlp1   = (const float*)d_in[2];
    const float* b_mlp1   = (const float*)d_in[3];
    const float* g1       = (const float*)d_in[4];
    const float* be1      = (const float*)d_in[5];
    const float* m1       = (const float*)d_in[6];
    const float* v1       = (const float*)d_in[7];
    const float* w_mlp2   = (const float*)d_in[8];
    const float* b_mlp2   = (const float*)d_in[9];
    const float* g2       = (const float*)d_in[10];
    const float* be2      = (const float*)d_in[11];
    const float* m2       = (const float*)d_in[12];
    const float* v2       = (const float*)d_in[13];
    const float* w_down1  = (const float*)d_in[14];
    const float* w_down2  = (const float*)d_in[15];
    const float* w_up     = (const float*)d_in[16];
    const float* b_up     = (const float*)d_in[17];
    const float* gu       = (const float*)d_in[18];
    const float* beu      = (const float*)d_in[19];
    const float* mu       = (const float*)d_in[20];
    const float* vu       = (const float*)d_in[21];
    // d_in[22] = k (always 20 for this problem; compiled in)

    prep_kernel<<<1, 256>>>(w_mlp1, b_mlp1, g1, be1, m1, v1,
                            w_mlp2, b_mlp2, g2, be2, m2, v2,
                            w_up, b_up, gu, beu, mu, vu);
    knn_kernel<<<dim3(NPT / 8, NB), 256>>>(xyz);
    pq_kernel<<<dim3(NPT / 16, NB), 128>>>(xyz, features);
    fenc_kernel<<<dim3(NPT / 8, NB), 128>>>();
    down_kernel<<<dim3(NPT / 8, NB), 256>>>(w_down1, w_down2);
    fch_kernel<<<1, CDD>>>();
    final_kernel<<<dim3(NPT / 32, NB), 256>>>((float*)d_out);
}

// round 10
// speedup vs baseline: 10.1505x; 1.5887x over previous
#include <cuda_runtime.h>
#include <math.h>

#define BN_EPS 1e-5f
#define NB 2
#define NC 128
#define NPT 4096
#define KK 20
#define CHH 64
#define CDD 16

// ---------------- device scratch (no allocations allowed) ----------------
__device__ int   d_idx[NB * NPT * KK];
__device__ float d_P[NB * NPT * NC];       // [b][n][c]  c<64: xyz-half, c>=64: feat-half
__device__ float d_Q[NB * NPT * NC];
__device__ float d_fenc[NB * NPT * NC];    // [b][n][c]
__device__ float d_f1[NB * NPT * CDD];     // [b][n][o]
__device__ float d_f2[NB * NPT * CDD];
__device__ float d_fsp[NPT];
__device__ float d_fch[CDD];
__device__ float d_fchpart[512 * CDD];
// folded weights
__device__ float d_w1p[CHH * 3], d_w1q[CHH * 3], d_b1f[CHH];
__device__ float d_w2p[CHH * NC], d_w2q[CHH * NC], d_b2f[CHH];
__device__ float d_wupf[NC * CDD], d_bupf[NC];

// ---------------- prep: fold BN + split weights ----------------
__global__ void prep_kernel(const float* w_mlp1, const float* b_mlp1,
                            const float* g1, const float* be1, const float* m1, const float* v1,
                            const float* w_mlp2, const float* b_mlp2,
                            const float* g2, const float* be2, const float* m2, const float* v2,
                            const float* w_up, const float* b_up,
                            const float* gu, const float* beu, const float* mu, const float* vu)
{
    int tid = threadIdx.x;
    for (int c = tid; c < CHH; c += blockDim.x) {
        float s = g1[c] * rsqrtf(v1[c] + BN_EPS);
        float t = be1[c] - m1[c] * s;
        d_b1f[c] = s * b_mlp1[c] + t;
        #pragma unroll
        for (int j = 0; j < 3; ++j) {
            float wx = w_mlp1[c * 6 + j];
            float wc = w_mlp1[c * 6 + 3 + j];
            d_w1p[c * 3 + j] = s * wx;
            d_w1q[c * 3 + j] = s * (wc - wx);
        }
        float s2 = g2[c] * rsqrtf(v2[c] + BN_EPS);
        float t2 = be2[c] - m2[c] * s2;
        d_b2f[c] = s2 * b_mlp2[c] + t2;
    }
    for (int i = tid; i < CHH * NC; i += blockDim.x) {
        int c = i >> 7;
        float s2 = g2[c] * rsqrtf(v2[c] + BN_EPS);
        int j = i & 127;
        float wa = w_mlp2[c * 256 + j];
        float wb = w_mlp2[c * 256 + 128 + j];
        d_w2p[i] = s2 * wa;
        d_w2q[i] = s2 * (wb - wa);
    }
    for (int i = tid; i < NC * CDD; i += blockDim.x) {
        int c = i >> 4;
        float su = gu[c] * rsqrtf(vu[c] + BN_EPS);
        d_wupf[i] = su * w_up[i];
    }
    for (int c = tid; c < NC; c += blockDim.x) {
        float su = gu[c] * rsqrtf(vu[c] + BN_EPS);
        d_bupf[c] = su * b_up[c] + (beu[c] - mu[c] * su);
    }
}

// ---------------- KNN: warp-shared top-20, lane-distributed list ----------------
// The row's running top-20 lives distributed across lanes 0..19 (1 reg each).
// `worst` is the TRUE global-so-far 20th distance -> acceptance rate drops from
// ~1800/row (per-lane lists) to ~130/row. Each insertion is warp-cooperative:
// ballot for position + one shfl_up shift (~10 instrs, no divergence: the
// while(mask) loop is warp-uniform).
#define ROWS_W 4   // rows per warp
__global__ void __launch_bounds__(256) knn_kernel(const float* __restrict__ xyz)
{
    __shared__ float sx[NPT];
    __shared__ float sy[NPT];
    __shared__ float sz[NPT];

    int b = blockIdx.y;
    const float* base = xyz + b * 3 * NPT;
    for (int i = threadIdx.x; i < NPT; i += 256) {
        sx[i] = base[i];
        sy[i] = base[NPT + i];
        sz[i] = base[2 * NPT + i];
    }
    __syncthreads();

    int warp = threadIdx.x >> 5;
    int lane = threadIdx.x & 31;
    const unsigned FULL = 0xffffffffu;

    for (int r = 0; r < ROWS_W; ++r) {
        int n = (blockIdx.x * 8 + warp) * ROWS_W + r;
        float xn = sx[n], yn = sy[n], zn = sz[n];

        float ld = 1e30f;   // lane `lane` holds list element `lane` (lane<KK)
        int   lj = 0;
        float worst = 1e30f;

        for (int j0 = 0; j0 < NPT; j0 += 32) {
            int j = j0 + lane;
            float dx = sx[j] - xn;
            float dy = sy[j] - yn;
            float dz = sz[j] - zn;
            float d = fmaf(dx, dx, fmaf(dy, dy, dz * dz));
            unsigned mask = __ballot_sync(FULL, d < worst);
            while (mask) {
                int src = __ffs(mask) - 1;
                mask &= mask - 1;
                float v = __shfl_sync(FULL, d, src);
                if (v < worst) {
                    int vj = j0 + src;
                    // position = first list slot with value > v
                    bool gt = (lane < KK) && (ld > v);
                    unsigned gm = __ballot_sync(FULL, gt);
                    int pos = __ffs(gm) - 1;   // gm != 0 since v < worst = ld@19
                    float ud = __shfl_up_sync(FULL, ld, 1);
                    int   uj = __shfl_up_sync(FULL, lj, 1);
                    if (lane > pos && lane < KK) { ld = ud; lj = uj; }
                    if (lane == pos)             { ld = v;  lj = vj; }
                    worst = __shfl_sync(FULL, ld, KK - 1);
                }
            }
        }
        if (lane < KK)
            d_idx[(b * NPT + n) * KK + lane] = lj;
    }
}

// ---------------- PQ: per-point projections (feat 128->64 for P and Q, plus xyz MLP) ----
__global__ void __launch_bounds__(128) pq_kernel(const float* __restrict__ xyz,
                                                 const float* __restrict__ features)
{
    __shared__ __align__(16) float s_f[NC * 16];  // [j][p]
    __shared__ float s_w[64 * 129];               // [j_local][cout] padded
    __shared__ float s_x[3 * 16];                 // [j][p]
    int b = blockIdx.y;
    int n0 = blockIdx.x * 16;
    int tid = threadIdx.x;

    for (int i = tid; i < NC * 16; i += 128) {
        int j = i >> 4, p = i & 15;
        s_f[i] = features[b * NC * NPT + j * NPT + n0 + p];
    }
    if (tid < 48) {
        int j = tid >> 4, p = tid & 15;
        s_x[tid] = xyz[b * 3 * NPT + j * NPT + n0 + p];
    }

    float acc[16];
    #pragma unroll
    for (int p = 0; p < 16; ++p) acc[p] = 0.f;
    int cout = tid;

    for (int jc = 0; jc < NC; jc += 64) {
        __syncthreads();
        for (int i = tid; i < 64 * 128; i += 128) {
            int jl = i & 63, co = i >> 6;
            float w = (co < 64) ? d_w2p[co * NC + jc + jl]
                                : d_w2q[(co - 64) * NC + jc + jl];
            s_w[jl * 129 + co] = w;
        }
        __syncthreads();
        #pragma unroll 4
        for (int jl = 0; jl < 64; ++jl) {
            float w = s_w[jl * 129 + cout];
            const float4* f4 = (const float4*)(s_f + (jc + jl) * 16);
            float fv[16];
            *(float4*)(fv + 0)  = f4[0];
            *(float4*)(fv + 4)  = f4[1];
            *(float4*)(fv + 8)  = f4[2];
            *(float4*)(fv + 12) = f4[3];
            #pragma unroll
            for (int p = 0; p < 16; ++p) acc[p] = fmaf(w, fv[p], acc[p]);
        }
    }

    if (cout < 64) {
        #pragma unroll
        for (int p = 0; p < 16; ++p)
            d_P[(b * NPT + n0 + p) * NC + 64 + cout] = acc[p];
        float w0 = d_w1p[cout * 3], w1 = d_w1p[cout * 3 + 1], w2 = d_w1p[cout * 3 + 2];
        #pragma unroll
        for (int p = 0; p < 16; ++p)
            d_P[(b * NPT + n0 + p) * NC + cout] =
                fmaf(w0, s_x[p], fmaf(w1, s_x[16 + p], w2 * s_x[32 + p]));
    } else {
        int cq = cout - 64;
        float bb = d_b2f[cq];
        #pragma unroll
        for (int p = 0; p < 16; ++p)
            d_Q[(b * NPT + n0 + p) * NC + 64 + cq] = acc[p] + bb;
        float w0 = d_w1q[cq * 3], w1 = d_w1q[cq * 3 + 1], w2 = d_w1q[cq * 3 + 2];
        float b1 = d_b1f[cq];
        #pragma unroll
        for (int p = 0; p < 16; ++p)
            d_Q[(b * NPT + n0 + p) * NC + cq] =
                fmaf(w0, s_x[p], fmaf(w1, s_x[16 + p], fmaf(w2, s_x[32 + p], b1)));
    }
}

// ---------------- f_enc: gather neighbors' P, max, add Q, relu ----------------
__global__ void __launch_bounds__(128) fenc_kernel()
{
    __shared__ int s_idx[8 * KK];
    int b = blockIdx.y, n0 = blockIdx.x * 8, tid = threadIdx.x;
    for (int i = tid; i < 8 * KK; i += 128)
        s_idx[i] = d_idx[(b * NPT + n0) * KK + i];
    __syncthreads();
    const float* Pb = d_P + b * NPT * NC;
    for (int p = 0; p < 8; ++p) {
        int n = n0 + p;
        float q = d_Q[(b * NPT + n) * NC + tid];
        float m = -1e30f;
        #pragma unroll
        for (int k = 0; k < KK; ++k) {
            int j = s_idx[p * KK + k];
            m = fmaxf(m, Pb[j * NC + tid]);
        }
        d_fenc[(b * NPT + n) * NC + tid] = fmaxf(q + m, 0.f);
    }
}

// ---------------- down-proj f1/f2 + f_space + f_channel partials ----------------
__global__ void __launch_bounds__(256) down_kernel(const float* __restrict__ wd1,
                                                   const float* __restrict__ wd2)
{
    __shared__ float s_fe[8 * NC];
    __shared__ float s_w[32 * 129];
    __shared__ float s_part[CDD * 9];
    int b = blockIdx.y, n0 = blockIdx.x * 8, tid = threadIdx.x;

    for (int i = tid; i < 32 * NC; i += 256) {
        int o = i >> 7, c = i & 127;
        float w = (o < 16) ? wd1[o * NC + c] : wd2[(o - 16) * NC + c];
        s_w[o * 129 + c] = w;
    }
    for (int i = tid; i < 8 * NC; i += 256)
        s_fe[i] = d_fenc[(b * NPT + n0) * NC + i];
    __syncthreads();

    int o = tid & 31, p = tid >> 5;
    const float* wr = s_w + o * 129;
    const float* fr = s_fe + p * NC;
    float a = 0.f;
    #pragma unroll 8
    for (int c = 0; c < NC; ++c) a = fmaf(wr[c], fr[c], a);
    a = fmaxf(a, 0.f);
    int n = n0 + p;
    if (o < 16) {
        d_f1[(b * NPT + n) * CDD + o] = a;
        if (b == 0) s_part[o * 9 + p] = a;
    } else {
        d_f2[(b * NPT + n) * CDD + (o - 16)] = a;
    }
    if (b == 0) {
        float v = (o >= 16) ? a : 0.f;
        #pragma unroll
        for (int off = 16; off > 0; off >>= 1)
            v += __shfl_down_sync(0xffffffffu, v, off);
        if (o == 0) d_fsp[n] = v * (1.f / 16.f);
        __syncthreads();
        if (tid < CDD) {
            float s = 0.f;
            #pragma unroll
            for (int p2 = 0; p2 < 8; ++p2) s += s_part[tid * 9 + p2];
            d_fchpart[blockIdx.x * CDD + tid] = s;
        }
    }
}

// ---------------- deterministic f_channel reduction ----------------
__global__ void fch_kernel()
{
    int o = threadIdx.x;
    float s = 0.f;
    for (int blk = 0; blk < 512; ++blk) s += d_fchpart[blk * CDD + o];
    d_fch[o] = s * (1.f / (float)NPT);
}

// ---------------- final: attention cross-term, up-proj+BN+relu, mish, transpose-store --
__global__ void __launch_bounds__(256) final_kernel(float* __restrict__ out)
{
    __shared__ float s_v[16 * 33];
    __shared__ float s_o[128 * 33];
    int b = blockIdx.y, n0 = blockIdx.x * 32, tid = threadIdx.x;

    for (int i = tid; i < 512; i += 256) {
        int o = i & 15, p = i >> 4;
        int n = n0 + p;
        float f1v = d_f1[(b * NPT + n) * CDD + o];
        float f2v = d_f2[(b * NPT + n) * CDD + o];
        float cross = sqrtf(fmaf(d_fch[o], d_fsp[n], 1e-12f));
        s_v[o * 33 + p] = cross + f1v + f2v;
    }
    __syncthreads();

    int c = tid & 127, ph = tid >> 7;
    float w16[16];
    #pragma unroll
    for (int o = 0; o < 16; ++o) w16[o] = d_wupf[c * CDD + o];
    float bup = d_bupf[c];

    for (int p = ph * 16; p < ph * 16 + 16; ++p) {
        float a = bup;
        #pragma unroll
        for (int o = 0; o < 16; ++o) a = fmaf(w16[o], s_v[o * 33 + p], a);
        float U = fmaxf(a, 0.f);
        float fe = d_fenc[(b * NPT + n0 + p) * NC + c];
        float x = fe - U;
        float sp = fmaxf(x, 0.f) + log1pf(expf(-fabsf(x)));
        s_o[c * 33 + p] = x * tanhf(sp);
    }
    __syncthreads();

    for (int i = tid; i < 128 * 32; i += 256) {
        int cc = i >> 5, p = i & 31;
        out[b * NC * NPT + cc * NPT + n0 + p] = s_o[cc * 33 + p];
    }
}

// ---------------- launch ----------------
extern "C" void kernel_launch(void* const* d_in, const int* in_sizes, int n_in,
                              void* d_out, int out_size)
{
    const float* xyz      = (const float*)d_in[0];
    const float* features = (const float*)d_in[1];
    const float* w_mlp1   = (const float*)d_in[2];
    const float* b_mlp1   = (const float*)d_in[3];
    const float* g1       = (const float*)d_in[4];
    const float* be1      = (const float*)d_in[5];
    const float* m1       = (const float*)d_in[6];
    const float* v1       = (const float*)d_in[7];
    const float* w_mlp2   = (const float*)d_in[8];
    const float* b_mlp2   = (const float*)d_in[9];
    const float* g2       = (const float*)d_in[10];
    const float* be2      = (const float*)d_in[11];
    const float* m2       = (const float*)d_in[12];
    const float* v2       = (const float*)d_in[13];
    const float* w_down1  = (const float*)d_in[14];
    const float* w_down2  = (const float*)d_in[15];
    const float* w_up     = (const float*)d_in[16];
    const float* b_up     = (const float*)d_in[17];
    const float* gu       = (const float*)d_in[18];
    const float* beu      = (const float*)d_in[19];
    const float* mu       = (const float*)d_in[20];
    const float* vu       = (const float*)d_in[21];
    // d_in[22] = k (always 20 for this problem; compiled in)

    prep_kernel<<<1, 256>>>(w_mlp1, b_mlp1, g1, be1, m1, v1,
                            w_mlp2, b_mlp2, g2, be2, m2, v2,
                            w_up, b_up, gu, beu, mu, vu);
    knn_kernel<<<dim3(NPT / (8 * ROWS_W), NB), 256>>>(xyz);
    pq_kernel<<<dim3(NPT / 16, NB), 128>>>(xyz, features);
    fenc_kernel<<<dim3(NPT / 8, NB), 128>>>();
    down_kernel<<<dim3(NPT / 8, NB), 256>>>(w_down1, w_down2);
    fch_kernel<<<1, CDD>>>();
    final_kernel<<<dim3(NPT / 32, NB), 256>>>((float*)d_out);
}

// round 11
// speedup vs baseline: 12.2987x; 1.2116x over previous
#include <cuda_runtime.h>
#include <math.h>

#define BN_EPS 1e-5f
#define NB 2
#define NC 128
#define NPT 4096
#define KK 20
#define CHH 64
#define CDD 16

// ---------------- device scratch (no allocations allowed) ----------------
__device__ int   d_idx[NB * NPT * KK];
__device__ float d_P[NB * NPT * NC];       // [b][n][c]  c<64: xyz-half, c>=64: feat-half
__device__ float d_Q[NB * NPT * NC];
__device__ float d_fenc[NB * NPT * NC];    // [b][n][c]
__device__ float d_f1[NB * NPT * CDD];     // [b][n][o]
__device__ float d_f2[NB * NPT * CDD];
__device__ float d_fsp[NPT];
__device__ float d_fch[CDD];
__device__ float d_fchpart[512 * CDD];

// ---------------- KNN: warp-shared top-20, 4 rows per warp ----------------
// Four rows' top-20 lists live lane-distributed (lanes 0..19, 1 reg each, per
// row). Per 32-candidate chunk: one float2+float LDS, 4 distances, 4 ballots.
// Insertions are warp-cooperative; `worst` is refreshed ONCE per accepting
// chunk (off the dependency chain) — the insertion ballot (ld > v) is
// self-guarding, so a stale `worst` only costs an occasional wasted attempt,
// never a wrong list. Semantics identical to the exact sequential insert
// (strict <, insert-after-equals, ascending j).
__global__ void __launch_bounds__(256) knn_kernel(const float* __restrict__ xyz)
{
    __shared__ float2 sxy[NPT];   // 32KB
    __shared__ float  szz[NPT];   // 16KB

    int b = blockIdx.y;
    const float* base = xyz + b * 3 * NPT;
    for (int i = threadIdx.x; i < NPT; i += 256) {
        sxy[i] = make_float2(base[i], base[NPT + i]);
        szz[i] = base[2 * NPT + i];
    }
    __syncthreads();

    int warp = threadIdx.x >> 5;
    int lane = threadIdx.x & 31;
    const unsigned FULL = 0xffffffffu;
    int n0 = (blockIdx.x * 8 + warp) * 4;

    float xn[4], yn[4], zn[4], ld[4], worst[4];
    int   lj[4];
    #pragma unroll
    for (int r = 0; r < 4; ++r) {
        float2 c = sxy[n0 + r];
        xn[r] = c.x; yn[r] = c.y; zn[r] = szz[n0 + r];
        ld[r] = 1e30f; lj[r] = 0; worst[r] = 1e30f;
    }

    for (int j0 = 0; j0 < NPT; j0 += 32) {
        float2 pxy = sxy[j0 + lane];
        float  pz  = szz[j0 + lane];
        float d[4];
        #pragma unroll
        for (int r = 0; r < 4; ++r) {
            float dx = pxy.x - xn[r];
            float dy = pxy.y - yn[r];
            float dz = pz    - zn[r];
            d[r] = fmaf(dx, dx, fmaf(dy, dy, dz * dz));
        }
        #pragma unroll
        for (int r = 0; r < 4; ++r) {
            unsigned mask = __ballot_sync(FULL, d[r] < worst[r]);
            if (mask) {
                do {
                    int src = __ffs(mask) - 1;
                    mask &= mask - 1;
                    float v = __shfl_sync(FULL, d[r], src);
                    bool gt = (lane < KK) && (ld[r] > v);
                    unsigned gm = __ballot_sync(FULL, gt);
                    if (gm) {                       // v < current 20th
                        int pos = __ffs(gm) - 1;
                        float ud = __shfl_up_sync(FULL, ld[r], 1);
                        int   uj = __shfl_up_sync(FULL, lj[r], 1);
                        if (lane > pos && lane < KK) { ld[r] = ud; lj[r] = uj; }
                        if (lane == pos)             { ld[r] = v;  lj[r] = j0 + src; }
                    }
                } while (mask);
                worst[r] = __shfl_sync(FULL, ld[r], KK - 1);
            }
        }
    }

    #pragma unroll
    for (int r = 0; r < 4; ++r)
        if (lane < KK)
            d_idx[(b * NPT + n0 + r) * KK + lane] = lj[r];
}

// ---------------- PQ: per-point projections, BN folded inline ----------------
__global__ void __launch_bounds__(128) pq_kernel(const float* __restrict__ xyz,
                                                 const float* __restrict__ features,
                                                 const float* __restrict__ w_mlp1,
                                                 const float* __restrict__ b_mlp1,
                                                 const float* __restrict__ g1,
                                                 const float* __restrict__ be1,
                                                 const float* __restrict__ m1,
                                                 const float* __restrict__ v1,
                                                 const float* __restrict__ w_mlp2,
                                                 const float* __restrict__ b_mlp2,
                                                 const float* __restrict__ g2,
                                                 const float* __restrict__ be2,
                                                 const float* __restrict__ m2,
                                                 const float* __restrict__ v2)
{
    __shared__ __align__(16) float s_f[NC * 16];  // [j][p]
    __shared__ float s_w[64 * 129];               // [j_local][cout] padded
    __shared__ float s_x[3 * 16];                 // [j][p]
    __shared__ float s_s2[64];                    // folded BN2 scale
    int b = blockIdx.y;
    int n0 = blockIdx.x * 16;
    int tid = threadIdx.x;

    for (int i = tid; i < NC * 16; i += 128) {
        int j = i >> 4, p = i & 15;
        s_f[i] = features[b * NC * NPT + j * NPT + n0 + p];
    }
    if (tid < 48) {
        int j = tid >> 4, p = tid & 15;
        s_x[tid] = xyz[b * 3 * NPT + j * NPT + n0 + p];
    }
    if (tid < 64)
        s_s2[tid] = g2[tid] * rsqrtf(v2[tid] + BN_EPS);

    float acc[16];
    #pragma unroll
    for (int p = 0; p < 16; ++p) acc[p] = 0.f;
    int cout = tid;

    for (int jc = 0; jc < NC; jc += 64) {
        __syncthreads();
        for (int i = tid; i < 64 * 128; i += 128) {
            int jl = i & 63, co = i >> 6;
            int cc = (co < 64) ? co : (co - 64);
            float wa = w_mlp2[cc * 256 + jc + jl];
            float w;
            if (co < 64) {
                w = s_s2[cc] * wa;
            } else {
                float wb = w_mlp2[cc * 256 + 128 + jc + jl];
                w = s_s2[cc] * (wb - wa);
            }
            s_w[jl * 129 + co] = w;
        }
        __syncthreads();
        #pragma unroll 4
        for (int jl = 0; jl < 64; ++jl) {
            float w = s_w[jl * 129 + cout];
            const float4* f4 = (const float4*)(s_f + (jc + jl) * 16);
            float fv[16];
            *(float4*)(fv + 0)  = f4[0];
            *(float4*)(fv + 4)  = f4[1];
            *(float4*)(fv + 8)  = f4[2];
            *(float4*)(fv + 12) = f4[3];
            #pragma unroll
            for (int p = 0; p < 16; ++p) acc[p] = fmaf(w, fv[p], acc[p]);
        }
    }

    if (cout < 64) {
        #pragma unroll
        for (int p = 0; p < 16; ++p)
            d_P[(b * NPT + n0 + p) * NC + 64 + cout] = acc[p];
        float s1 = g1[cout] * rsqrtf(v1[cout] + BN_EPS);
        float w0 = s1 * w_mlp1[cout * 6 + 0];
        float w1 = s1 * w_mlp1[cout * 6 + 1];
        float w2 = s1 * w_mlp1[cout * 6 + 2];
        #pragma unroll
        for (int p = 0; p < 16; ++p)
            d_P[(b * NPT + n0 + p) * NC + cout] =
                fmaf(w0, s_x[p], fmaf(w1, s_x[16 + p], w2 * s_x[32 + p]));
    } else {
        int cq = cout - 64;
        float s2v = s_s2[cq];
        float bb = s2v * b_mlp2[cq] + (be2[cq] - m2[cq] * s2v);
        #pragma unroll
        for (int p = 0; p < 16; ++p)
            d_Q[(b * NPT + n0 + p) * NC + 64 + cq] = acc[p] + bb;
        float s1 = g1[cq] * rsqrtf(v1[cq] + BN_EPS);
        float w0 = s1 * (w_mlp1[cq * 6 + 3] - w_mlp1[cq * 6 + 0]);
        float w1 = s1 * (w_mlp1[cq * 6 + 4] - w_mlp1[cq * 6 + 1]);
        float w2 = s1 * (w_mlp1[cq * 6 + 5] - w_mlp1[cq * 6 + 2]);
        float b1 = s1 * b_mlp1[cq] + (be1[cq] - m1[cq] * s1);
        #pragma unroll
        for (int p = 0; p < 16; ++p)
            d_Q[(b * NPT + n0 + p) * NC + cq] =
                fmaf(w0, s_x[p], fmaf(w1, s_x[16 + p], fmaf(w2, s_x[32 + p], b1)));
    }
}

// ---------------- f_enc: gather neighbors' P, max, add Q, relu ----------------
__global__ void __launch_bounds__(128) fenc_kernel()
{
    __shared__ int s_idx[8 * KK];
    int b = blockIdx.y, n0 = blockIdx.x * 8, tid = threadIdx.x;
    for (int i = tid; i < 8 * KK; i += 128)
        s_idx[i] = d_idx[(b * NPT + n0) * KK + i] * NC;   // pre-scale
    __syncthreads();
    const float* Pb = d_P + b * NPT * NC;
    for (int p = 0; p < 8; ++p) {
        int n = n0 + p;
        float q = d_Q[(b * NPT + n) * NC + tid];
        float m = -1e30f;
        #pragma unroll
        for (int k = 0; k < KK; ++k) {
            int j = s_idx[p * KK + k];
            m = fmaxf(m, Pb[j + tid]);
        }
        d_fenc[(b * NPT + n) * NC + tid] = fmaxf(q + m, 0.f);
    }
}

// ---------------- down-proj f1/f2 + f_space + f_channel partials ----------------
__global__ void __launch_bounds__(256) down_kernel(const float* __restrict__ wd1,
                                                   const float* __restrict__ wd2)
{
    __shared__ float s_fe[8 * NC];
    __shared__ float s_w[32 * 129];
    __shared__ float s_part[CDD * 9];
    int b = blockIdx.y, n0 = blockIdx.x * 8, tid = threadIdx.x;

    for (int i = tid; i < 32 * NC; i += 256) {
        int o = i >> 7, c = i & 127;
        float w = (o < 16) ? wd1[o * NC + c] : wd2[(o - 16) * NC + c];
        s_w[o * 129 + c] = w;
    }
    for (int i = tid; i < 8 * NC; i += 256)
        s_fe[i] = d_fenc[(b * NPT + n0) * NC + i];
    __syncthreads();

    int o = tid & 31, p = tid >> 5;
    const float* wr = s_w + o * 129;
    const float* fr = s_fe + p * NC;
    float a = 0.f;
    #pragma unroll 8
    for (int c = 0; c < NC; ++c) a = fmaf(wr[c], fr[c], a);
    a = fmaxf(a, 0.f);
    int n = n0 + p;
    if (o < 16) {
        d_f1[(b * NPT + n) * CDD + o] = a;
        if (b == 0) s_part[o * 9 + p] = a;
    } else {
        d_f2[(b * NPT + n) * CDD + (o - 16)] = a;
    }
    if (b == 0) {
        float v = (o >= 16) ? a : 0.f;
        #pragma unroll
        for (int off = 16; off > 0; off >>= 1)
            v += __shfl_down_sync(0xffffffffu, v, off);
        if (o == 0) d_fsp[n] = v * (1.f / 16.f);
        __syncthreads();
        if (tid < CDD) {
            float s = 0.f;
            #pragma unroll
            for (int p2 = 0; p2 < 8; ++p2) s += s_part[tid * 9 + p2];
            d_fchpart[blockIdx.x * CDD + tid] = s;
        }
    }
}

// ---------------- deterministic f_channel reduction (widened) ----------------
__global__ void fch_kernel()
{
    __shared__ float s[CDD][17];
    int t = threadIdx.x;              // 256 threads
    int o = t & 15, cb = t >> 4;      // 16 chunks of 32 blocks
    float p = 0.f;
    #pragma unroll 8
    for (int i = 0; i < 32; ++i)
        p += d_fchpart[(cb * 32 + i) * CDD + o];
    s[o][cb] = p;
    __syncthreads();
    if (t < CDD) {
        float sum = 0.f;
        #pragma unroll
        for (int c2 = 0; c2 < 16; ++c2) sum += s[t][c2];
        d_fch[t] = sum * (1.f / (float)NPT);
    }
}

// ---------------- final: cross-term, up-proj+BN(folded)+relu, mish, store ----
__global__ void __launch_bounds__(256) final_kernel(float* __restrict__ out,
                                                    const float* __restrict__ w_up,
                                                    const float* __restrict__ b_up,
                                                    const float* __restrict__ gu,
                                                    const float* __restrict__ beu,
                                                    const float* __restrict__ mu,
                                                    const float* __restrict__ vu)
{
    __shared__ float s_v[16 * 33];
    __shared__ float s_o[128 * 33];
    int b = blockIdx.y, n0 = blockIdx.x * 32, tid = threadIdx.x;

    for (int i = tid; i < 512; i += 256) {
        int o = i & 15, p = i >> 4;
        int n = n0 + p;
        float f1v = d_f1[(b * NPT + n) * CDD + o];
        float f2v = d_f2[(b * NPT + n) * CDD + o];
        float cross = sqrtf(fmaf(d_fch[o], d_fsp[n], 1e-12f));
        s_v[o * 33 + p] = cross + f1v + f2v;
    }
    __syncthreads();

    int c = tid & 127, ph = tid >> 7;
    float su = gu[c] * rsqrtf(vu[c] + BN_EPS);
    float w16[16];
    #pragma unroll
    for (int o = 0; o < 16; ++o) w16[o] = su * w_up[c * CDD + o];
    float bup = su * b_up[c] + (beu[c] - mu[c] * su);

    for (int p = ph * 16; p < ph * 16 + 16; ++p) {
        float a = bup;
        #pragma unroll
        for (int o = 0; o < 16; ++o) a = fmaf(w16[o], s_v[o * 33 + p], a);
        float U = fmaxf(a, 0.f);
        float fe = d_fenc[(b * NPT + n0 + p) * NC + c];
        float x = fe - U;
        float sp = fmaxf(x, 0.f) + log1pf(expf(-fabsf(x)));
        s_o[c * 33 + p] = x * tanhf(sp);
    }
    __syncthreads();

    for (int i = tid; i < 128 * 32; i += 256) {
        int cc = i >> 5, p = i & 31;
        out[b * NC * NPT + cc * NPT + n0 + p] = s_o[cc * 33 + p];
    }
}

// ---------------- launch ----------------
extern "C" void kernel_launch(void* const* d_in, const int* in_sizes, int n_in,
                              void* d_out, int out_size)
{
    const float* xyz      = (const float*)d_in[0];
    const float* features = (const float*)d_in[1];
    const float* w_mlp1   = (const float*)d_in[2];
    const float* b_mlp1   = (const float*)d_in[3];
    const float* g1       = (const float*)d_in[4];
    const float* be1      = (const float*)d_in[5];
    const float* m1       = (const float*)d_in[6];
    const float* v1       = (const float*)d_in[7];
    const float* w_mlp2   = (const float*)d_in[8];
    const float* b_mlp2   = (const float*)d_in[9];
    const float* g2       = (const float*)d_in[10];
    const float* be2      = (const float*)d_in[11];
    const float* m2       = (const float*)d_in[12];
    const float* v2       = (const float*)d_in[13];
    const float* w_down1  = (const float*)d_in[14];
    const float* w_down2  = (const float*)d_in[15];
    const float* w_up     = (const float*)d_in[16];
    const float* b_up     = (const float*)d_in[17];
    const float* gu       = (const float*)d_in[18];
    const float* beu      = (const float*)d_in[19];
    const float* mu       = (const float*)d_in[20];
    const float* vu       = (const float*)d_in[21];
    // d_in[22] = k (always 20 for this problem; compiled in)

    knn_kernel<<<dim3(NPT / 32, NB), 256>>>(xyz);
    pq_kernel<<<dim3(NPT / 16, NB), 128>>>(xyz, features,
                                           w_mlp1, b_mlp1, g1, be1, m1, v1,
                                           w_mlp2, b_mlp2, g2, be2, m2, v2);
    fenc_kernel<<<dim3(NPT / 8, NB), 128>>>();
    down_kernel<<<dim3(NPT / 8, NB), 256>>>(w_down1, w_down2);
    fch_kernel<<<1, 256>>>();
    final_kernel<<<dim3(NPT / 32, NB), 256>>>((float*)d_out,
                                              w_up, b_up, gu, beu, mu, vu);
}